// round 8
// baseline (speedup 1.0000x reference)
#include <cuda_runtime.h>
#include <cuda_fp16.h>
#include <cstdint>

// ============================================================
// 3-layer SNN. B=16384, H=512, 127 steps. Rows are independent across the
// ENTIRE simulation -> one persistent kernel, grid 128 CTAs x 128 rows,
// t-loop inside, zero global syncs.
//  - layer-0 spikes precomputed once as bits (m0 recurrence is input-only)
//  - layer-1: h1 = spk0(bits) @ W1 (2 exact fp16 splits), LIF -> spk1 bits
//    kept in SMEM
//  - layer-2: h2 = spk1(smem bits) @ W2 (2 splits), LIF -> s2/m2 (m2 = out)
// Engine: mma.sync m16n8k16 fp16, fp32 accum (same numerics as R7).
// ============================================================

constexpr int NSTEP = 127;
#define NELEM (16384 * 512)

__device__ float g_h0[NELEM];
__device__ float g_s1[NELEM];
__device__ float g_m1[NELEM];
__device__ float g_s2[NELEM];
__device__ uint32_t g_bits[(size_t)NSTEP * 16 * 16384];  // [t][kword][row]
__device__ __half g_W1t[2][512 * 512];   // [split][N][K] K-contiguous
__device__ __half g_W2t[2][512 * 512];

// ---- PTX helpers (sm_80-class, valid at sm_103 base target) ----
__device__ __forceinline__ uint32_t smem_to_u32(const void* p) {
    uint32_t a;
    asm("{ .reg .u64 t; cvta.to.shared.u64 t, %1; cvt.u32.u64 %0, t; }"
        : "=r"(a) : "l"(p));
    return a;
}
__device__ __forceinline__ void cp16(uint32_t dst, const void* src) {
    asm volatile("cp.async.cg.shared.global [%0], [%1], 16;"
                 :: "r"(dst), "l"(src) : "memory");
}
#define CP_COMMIT() asm volatile("cp.async.commit_group;" ::: "memory")
#define CP_WAIT(N)  asm volatile("cp.async.wait_group %0;" :: "n"(N) : "memory")

__device__ __forceinline__ void ldm4(uint32_t& r0, uint32_t& r1, uint32_t& r2,
                                     uint32_t& r3, uint32_t addr) {
    asm volatile("ldmatrix.sync.aligned.m8n8.x4.shared.b16 {%0,%1,%2,%3}, [%4];"
                 : "=r"(r0), "=r"(r1), "=r"(r2), "=r"(r3) : "r"(addr));
}
__device__ __forceinline__ void mma16816(float* c, const uint32_t* a,
                                         uint32_t b0, uint32_t b1) {
    asm volatile(
        "mma.sync.aligned.m16n8k16.row.col.f32.f16.f16.f32 "
        "{%0,%1,%2,%3}, {%4,%5,%6,%7}, {%8,%9}, {%0,%1,%2,%3};"
        : "+f"(c[0]), "+f"(c[1]), "+f"(c[2]), "+f"(c[3])
        : "r"(a[0]), "r"(a[1]), "r"(a[2]), "r"(a[3]), "r"(b0), "r"(b1));
}
#define SWZ64(x) ((x) ^ (((x) >> 3) & 0x30))

// smem map (dynamic):
//  [0, 16384)          A panels: 2 x 8KB (fp16 128r x 32k, SW64)
//  [16384, 65536)      B stages: 3 x 16KB (2 splits x [128n][32k], SW64)
//  [65536, 73728)      spk1 bits: [16 kwords][128 rows] u32
constexpr int SMEM_B   = 16384;
constexpr int SMEM_SPK = 65536;
constexpr int SMEM_TOT = 73728;

// ============================================================
// one-time kernels
// ============================================================
__global__ void zero_kernel(float4* __restrict__ out) {
    int i = blockIdx.x * blockDim.x + threadIdx.x;
    float4 z = make_float4(0.f, 0.f, 0.f, 0.f);
    ((float4*)g_s1)[i] = z;
    ((float4*)g_m1)[i] = z;
    ((float4*)g_s2)[i] = z;
    out[i] = z;
}

// exact 2-way fp16 split + transpose of W [512K x 512N] -> Wt[2][N][K]
template <int WHICH>
__global__ void prep_kernel(const float* __restrict__ Wsrc) {
    int idx = blockIdx.x * blockDim.x + threadIdx.x;  // over 512*512
    int k = idx >> 9, n = idx & 511;
    float w = Wsrc[idx];
    __half hi = __float2half_rn(w);
    __half lo = __float2half_rn(w - __half2float(hi));
    __half (*dst)[512 * 512] = (WHICH == 1) ? g_W1t : g_W2t;
    int t = n * 512 + k;
    dst[0][t] = hi;
    dst[1][t] = lo;
}

// layer-0 spike trajectories -> bits. warp g: row b = g & 16383, kword c = g >> 14
__global__ void spikes0_kernel() {
    int g = blockIdx.x * 8 + (threadIdx.x >> 5);
    int lane = threadIdx.x & 31;
    int b = g & 16383, c = g >> 14;
    float h = g_h0[(size_t)b * 512 + c * 32 + lane];
    float m = 0.f;
    for (int t = 0; t < NSTEP; t++) {
        m = 0.85f * m + h;
        bool p = m > 1.0f;
        unsigned bits = __ballot_sync(0xFFFFFFFFu, p);
        if (p) m = 0.f;
        if (lane == 0) g_bits[((size_t)t * 16 + c) * 16384 + b] = bits;
    }
}

// ============================================================
// layer-0 drive: h0 = relu_concat(inputs) @ W0 (fp32, runs once)
// ============================================================
__global__ __launch_bounds__(256)
void gemm0_kernel(const float* __restrict__ Aext, const float* __restrict__ W) {
    constexpr int KT = 8, NK = 256 / KT;
    __shared__ float As[2][KT][128];
    __shared__ float Bs[2][KT][128];
    const int row0 = blockIdx.x * 128, col0 = blockIdx.y * 128;
    const int tid = threadIdx.x;
    const int tx = tid & 15, ty = tid >> 4;
    const int ar = tid >> 1, aq = (tid & 1) * 4;
    const int bk = tid >> 5, bj = (tid & 31) * 4;

    float acc[8][8];
#pragma unroll
    for (int i = 0; i < 8; i++)
#pragma unroll
        for (int j = 0; j < 8; j++) acc[i][j] = 0.f;

    float4 ra, rb;
    auto LOADG = [&](int k0) {
        int kk = k0 + aq;
        if (kk < 128) {
            float4 v = *(const float4*)(Aext + (size_t)(row0 + ar) * 128 + kk);
            ra.x = fmaxf(v.x, 0.f); ra.y = fmaxf(v.y, 0.f);
            ra.z = fmaxf(v.z, 0.f); ra.w = fmaxf(v.w, 0.f);
        } else {
            float4 v = *(const float4*)(Aext + (size_t)(row0 + ar) * 128 + (kk - 128));
            ra.x = fmaxf(-v.x, 0.f); ra.y = fmaxf(-v.y, 0.f);
            ra.z = fmaxf(-v.z, 0.f); ra.w = fmaxf(-v.w, 0.f);
        }
        rb = *(const float4*)(W + (size_t)(k0 + bk) * 512 + col0 + bj);
    };
    auto STORES = [&](int buf) {
        As[buf][aq + 0][ar] = ra.x; As[buf][aq + 1][ar] = ra.y;
        As[buf][aq + 2][ar] = ra.z; As[buf][aq + 3][ar] = ra.w;
        *(float4*)&Bs[buf][bk][bj] = rb;
    };

    LOADG(0); STORES(0); __syncthreads();
    for (int kt = 0; kt < NK; kt++) {
        const int buf = kt & 1;
        if (kt + 1 < NK) LOADG((kt + 1) * KT);
#pragma unroll
        for (int k = 0; k < KT; k++) {
            float4 a0 = *(const float4*)&As[buf][k][ty * 8];
            float4 a1 = *(const float4*)&As[buf][k][ty * 8 + 4];
            float4 b0 = *(const float4*)&Bs[buf][k][tx * 8];
            float4 b1 = *(const float4*)&Bs[buf][k][tx * 8 + 4];
            float av[8] = {a0.x, a0.y, a0.z, a0.w, a1.x, a1.y, a1.z, a1.w};
            float bv[8] = {b0.x, b0.y, b0.z, b0.w, b1.x, b1.y, b1.z, b1.w};
#pragma unroll
            for (int i = 0; i < 8; i++)
#pragma unroll
                for (int j = 0; j < 8; j++) acc[i][j] = fmaf(av[i], bv[j], acc[i][j]);
        }
        if (kt + 1 < NK) STORES(buf ^ 1);
        __syncthreads();
    }
    const int r0 = row0 + ty * 8, c0 = col0 + tx * 8;
#pragma unroll
    for (int i = 0; i < 8; i++) {
        size_t base = (size_t)(r0 + i) * 512 + c0;
        *(float4*)&g_h0[base]     = make_float4(acc[i][0], acc[i][1], acc[i][2], acc[i][3]);
        *(float4*)&g_h0[base + 4] = make_float4(acc[i][4], acc[i][5], acc[i][6], acc[i][7]);
    }
}

// ============================================================
// fused per-tile GEMM + LIF (called from the persistent kernel)
// Tile: 128 rows x 128 cols (col0 = nt*128), K=512 in 16 chunks of 32.
// 8 warps, warp tile 64x32 (warp_m = wid&1, warp_n = wid>>1).
// ============================================================
template <int LAYER>
__device__ __forceinline__ void gemm_tile(const uint32_t sb, const int t,
                                          const int nt, const int row0,
                                          const int tid,
                                          float* __restrict__ Mout) {
    const int wid = tid >> 5, lane = tid & 31;
    const int warp_m = wid & 1, warp_n = wid >> 1;
    const int mat = lane >> 3, mrr = lane & 7;
    const int col0 = nt * 128;
    const __half* W = (LAYER == 1) ? &g_W1t[0][0] : &g_W2t[0][0];
    const uint32_t* bt =
        g_bits + ((size_t)t * 16) * 16384 + row0;   // layer-1 bit source

    // B chunk loader: [2 splits][128n][32k] fp16, SW64, stage (c%3)
    auto load_B = [&](int c) {
        const uint32_t bp = sb + SMEM_B + (c % 3) * 16384;
        const int k0 = c * 32;
#pragma unroll
        for (int j = 0; j < 4; j++) {
            int i = tid + j * 256;
            int sp = i >> 9, rem = i & 511;
            int n = rem >> 2, q = rem & 3;
            cp16(bp + sp * 8192 + SWZ64(n * 64 + q * 16),
                 W + (size_t)sp * 262144 + (size_t)(col0 + n) * 512 + k0 + q * 8);
        }
        CP_COMMIT();
    };

    // A chunk decoder: bits -> fp16 0/1 panel (c&1), SW64. 2 threads/row.
    auto decode_A = [&](int c) {
        const int r = tid >> 1, hsel = tid & 1;
        uint32_t w;
        if (LAYER == 1) {
            w = bt[(size_t)c * 16384 + r];
        } else {
            asm volatile("ld.shared.b32 %0, [%1];"
                         : "=r"(w) : "r"(sb + SMEM_SPK + (c * 128 + r) * 4));
        }
        const uint32_t pan = sb + (c & 1) * 8192;
#pragma unroll
        for (int qq = 0; qq < 2; qq++) {
            const int q = hsel * 2 + qq;
            uint32_t h2[4];
#pragma unroll
            for (int i = 0; i < 4; i++) {
                uint32_t x = (w >> (q * 8 + i * 2)) & 3u;
                h2[i] = (x & 1u) * 0x3C00u + (x >> 1) * 0x3C000000u;
            }
            asm volatile("st.shared.v4.b32 [%0], {%1,%2,%3,%4};"
                         :: "r"(pan + SWZ64((uint32_t)(r * 64 + q * 16))),
                            "r"(h2[0]), "r"(h2[1]), "r"(h2[2]), "r"(h2[3]));
        }
    };

    float acc[4][4][4];
#pragma unroll
    for (int mt = 0; mt < 4; mt++)
#pragma unroll
        for (int nb = 0; nb < 4; nb++)
#pragma unroll
            for (int e = 0; e < 4; e++) acc[mt][nb][e] = 0.f;

    decode_A(0);
    load_B(0);
    load_B(1);

#pragma unroll 1
    for (int c = 0; c < 16; c++) {
        if (c < 15) CP_WAIT(1); else CP_WAIT(0);
        __syncthreads();
        if (c + 2 < 16) load_B(c + 2);
        if (c + 1 < 16) decode_A(c + 1);

        const uint32_t ab = sb + (c & 1) * 8192;
        const uint32_t bb = sb + SMEM_B + (c % 3) * 16384;
#pragma unroll
        for (int k16 = 0; k16 < 2; k16++) {
            const int k0 = k16 * 16;
            uint32_t a[4][4];
#pragma unroll
            for (int mt = 0; mt < 4; mt++) {
                int row = warp_m * 64 + mt * 16 + (mat & 1) * 8 + mrr;
                int kk  = k0 + (mat >> 1) * 8;
                ldm4(a[mt][0], a[mt][1], a[mt][2], a[mt][3],
                     ab + SWZ64((uint32_t)(row * 64 + kk * 2)));
            }
#pragma unroll
            for (int sp = 0; sp < 2; sp++) {
                uint32_t b[2][4];
#pragma unroll
                for (int n2 = 0; n2 < 2; n2++) {
                    int n  = warp_n * 32 + n2 * 16 + (mat >> 1) * 8 + mrr;
                    int kk = k0 + (mat & 1) * 8;
                    ldm4(b[n2][0], b[n2][1], b[n2][2], b[n2][3],
                         bb + sp * 8192 + SWZ64((uint32_t)(n * 64 + kk * 2)));
                }
#pragma unroll
                for (int mt = 0; mt < 4; mt++)
#pragma unroll
                    for (int nb = 0; nb < 4; nb++)
                        mma16816(acc[mt][nb], a[mt],
                                 b[nb >> 1][(nb & 1) * 2],
                                 b[nb >> 1][(nb & 1) * 2 + 1]);
            }
        }
    }

    // ---- fused LIF epilogue (register-direct) ----
    const int er = row0 + warp_m * 64 + (lane >> 2);
    const int ecb = col0 + warp_n * 32 + (lane & 3) * 2;
    if (LAYER == 1) {
#pragma unroll
        for (int mt = 0; mt < 4; mt++)
#pragma unroll
            for (int hrow = 0; hrow < 2; hrow++) {
                const int r = er + mt * 16 + hrow * 8;
                uint32_t pb = 0;
#pragma unroll
                for (int nb = 0; nb < 4; nb++) {
                    size_t ix = (size_t)r * 512 + ecb + nb * 8;
                    float2 sv = *(const float2*)(g_s1 + ix);
                    float2 mv = *(const float2*)(g_m1 + ix);
                    sv.x = 0.9f * sv.x + acc[mt][nb][hrow * 2 + 0];
                    mv.x = 0.85f * mv.x + sv.x;
                    sv.y = 0.9f * sv.y + acc[mt][nb][hrow * 2 + 1];
                    mv.y = 0.85f * mv.y + sv.y;
                    uint32_t b0 = (mv.x > 1.f) ? 1u : 0u;
                    uint32_t b1 = (mv.y > 1.f) ? 1u : 0u;
                    if (mv.x > 1.f) mv.x = 0.f;
                    if (mv.y > 1.f) mv.y = 0.f;
                    pb |= (b0 | (b1 << 1)) << (nb * 8 + (lane & 3) * 2);
                    *(float2*)(g_s1 + ix) = sv;
                    *(float2*)(g_m1 + ix) = mv;
                }
                pb |= __shfl_xor_sync(0xFFFFFFFFu, pb, 1);
                pb |= __shfl_xor_sync(0xFFFFFFFFu, pb, 2);
                if ((lane & 3) == 0) {
                    int word = nt * 4 + warp_n;
                    asm volatile("st.shared.b32 [%0], %1;"
                        :: "r"(sb + SMEM_SPK + (word * 128 + (r - row0)) * 4),
                           "r"(pb));
                }
            }
    } else {
#pragma unroll
        for (int mt = 0; mt < 4; mt++)
#pragma unroll
            for (int hrow = 0; hrow < 2; hrow++) {
                const int r = er + mt * 16 + hrow * 8;
#pragma unroll
                for (int nb = 0; nb < 4; nb++) {
                    size_t ix = (size_t)r * 512 + ecb + nb * 8;
                    float2 sv = *(const float2*)(g_s2 + ix);
                    float2 mv = *(const float2*)(Mout + ix);
                    sv.x = 0.9f * sv.x + acc[mt][nb][hrow * 2 + 0];
                    mv.x = 0.85f * mv.x + sv.x;
                    sv.y = 0.9f * sv.y + acc[mt][nb][hrow * 2 + 1];
                    mv.y = 0.85f * mv.y + sv.y;
                    *(float2*)(g_s2 + ix) = sv;
                    *(float2*)(Mout + ix) = mv;
                }
            }
    }
    // barrier AFTER epilogue: next tile's stage-0/panel-0 writes are WAR-safe,
    // and layer-1 spk-bit STS become visible before layer-2 decodes.
    __syncthreads();
}

// ============================================================
// persistent kernel: 128 CTAs x 128 rows, full 127-step simulation
// ============================================================
__global__ __launch_bounds__(256, 1)
void snn_kernel(float* __restrict__ out) {
    extern __shared__ char smem[];
    const uint32_t sb = smem_to_u32(smem);
    const int tid = threadIdx.x;
    const int row0 = blockIdx.x * 128;

#pragma unroll 1
    for (int t = 0; t < NSTEP; t++) {
#pragma unroll 1
        for (int nt = 0; nt < 4; nt++)
            gemm_tile<1>(sb, t, nt, row0, tid, out);
#pragma unroll 1
        for (int nt = 0; nt < 4; nt++)
            gemm_tile<2>(sb, t, nt, row0, tid, out);
    }
}

// ============================================================
// launch
// ============================================================
extern "C" void kernel_launch(void* const* d_in, const int* in_sizes, int n_in,
                              void* d_out, int out_size) {
    (void)in_sizes; (void)n_in; (void)out_size;
    const float* inp = (const float*)d_in[0];   // [16384, 128]
    const float* W0  = (const float*)d_in[1];   // [256, 512]
    const float* W1  = (const float*)d_in[2];   // [512, 512]
    const float* W2  = (const float*)d_in[3];   // [512, 512]
    float* out = (float*)d_out;                 // m2 state [16384, 512]

    cudaFuncSetAttribute(snn_kernel,
                         cudaFuncAttributeMaxDynamicSharedMemorySize, SMEM_TOT);

    zero_kernel<<<(NELEM / 4) / 256, 256>>>((float4*)out);
    prep_kernel<1><<<1024, 256>>>(W1);
    prep_kernel<2><<<1024, 256>>>(W2);
    gemm0_kernel<<<dim3(128, 4), 256>>>(inp, W0);
    spikes0_kernel<<<32768, 256>>>();
    snn_kernel<<<128, 256, SMEM_TOT>>>(out);
}

// round 9
// speedup vs baseline: 1.3024x; 1.3024x over previous
#include <cuda_runtime.h>
#include <cuda_fp16.h>
#include <cstdint>

// ============================================================
// 3-layer SNN. B=16384, H=512, 127 steps.
// R9 = R7 launch shell (2 GEMM kernels/step, grid 128x4, 2 CTAs/SM)
//      + spike-bit compression from R8:
//  - layer-0 spikes precomputed ONCE as bits (m0 recurrence is input-only):
//    kills per-step m0/h0/spk0 DRAM traffic
//  - spk1 stored as a 1MB global bit array (pack in gemm1 epilogue via
//    shfl-OR, decode to fp16 smem panels in gemm2)
// Engine: mma.sync m16n8k16 fp16, 2 exact fp16 W-splits, fp32 accum
// (identical MMA order to R7/R8 -> expect bit-identical rel_err).
// ============================================================

constexpr int NSTEP = 127;
#define NELEM (16384 * 512)

__device__ float g_h0[NELEM];
__device__ float g_s1[NELEM];
__device__ float g_m1[NELEM];
__device__ float g_s2[NELEM];
__device__ uint32_t g_bits0[(size_t)NSTEP * 16 * 16384];  // [t][kword][row]
__device__ uint32_t g_bits1[16 * 16384];                  // [kword][row]
__device__ __half g_W1t[2][512 * 512];   // [split][N][K] K-contiguous
__device__ __half g_W2t[2][512 * 512];

// ---- PTX helpers (sm_80-class, valid at sm_103 base target) ----
__device__ __forceinline__ uint32_t smem_to_u32(const void* p) {
    uint32_t a;
    asm("{ .reg .u64 t; cvta.to.shared.u64 t, %1; cvt.u32.u64 %0, t; }"
        : "=r"(a) : "l"(p));
    return a;
}
__device__ __forceinline__ void cp16(uint32_t dst, const void* src) {
    asm volatile("cp.async.cg.shared.global [%0], [%1], 16;"
                 :: "r"(dst), "l"(src) : "memory");
}
#define CP_COMMIT() asm volatile("cp.async.commit_group;" ::: "memory")
#define CP_WAIT(N)  asm volatile("cp.async.wait_group %0;" :: "n"(N) : "memory")

__device__ __forceinline__ void ldm4(uint32_t& r0, uint32_t& r1, uint32_t& r2,
                                     uint32_t& r3, uint32_t addr) {
    asm volatile("ldmatrix.sync.aligned.m8n8.x4.shared.b16 {%0,%1,%2,%3}, [%4];"
                 : "=r"(r0), "=r"(r1), "=r"(r2), "=r"(r3) : "r"(addr));
}
__device__ __forceinline__ void mma16816(float* c, const uint32_t* a,
                                         uint32_t b0, uint32_t b1) {
    asm volatile(
        "mma.sync.aligned.m16n8k16.row.col.f32.f16.f16.f32 "
        "{%0,%1,%2,%3}, {%4,%5,%6,%7}, {%8,%9}, {%0,%1,%2,%3};"
        : "+f"(c[0]), "+f"(c[1]), "+f"(c[2]), "+f"(c[3])
        : "r"(a[0]), "r"(a[1]), "r"(a[2]), "r"(a[3]), "r"(b0), "r"(b1));
}
#define SWZ64(x) ((x) ^ (((x) >> 3) & 0x30))

// smem: [0,16384) A panels 2x8KB ; [16384,65536) B stages 3x16KB
constexpr int SMEM_B   = 16384;
constexpr int SMEM_TOT = 65536;                 // 64KB -> 2 CTAs/SM

// ============================================================
// one-time kernels
// ============================================================
__global__ void zero_kernel(float4* __restrict__ out) {
    int i = blockIdx.x * blockDim.x + threadIdx.x;
    float4 z = make_float4(0.f, 0.f, 0.f, 0.f);
    ((float4*)g_s1)[i] = z;
    ((float4*)g_m1)[i] = z;
    ((float4*)g_s2)[i] = z;
    out[i] = z;
}

// exact 2-way fp16 split + transpose of W [512K x 512N] -> Wt[2][N][K]
template <int WHICH>
__global__ void prep_kernel(const float* __restrict__ Wsrc) {
    int idx = blockIdx.x * blockDim.x + threadIdx.x;  // over 512*512
    int k = idx >> 9, n = idx & 511;
    float w = Wsrc[idx];
    __half hi = __float2half_rn(w);
    __half lo = __float2half_rn(w - __half2float(hi));
    __half (*dst)[512 * 512] = (WHICH == 1) ? g_W1t : g_W2t;
    int t = n * 512 + k;
    dst[0][t] = hi;
    dst[1][t] = lo;
}

// layer-0 spike trajectories -> bits. warp g: row b = g & 16383, kword c = g >> 14
__global__ void spikes0_kernel() {
    int g = blockIdx.x * 8 + (threadIdx.x >> 5);
    int lane = threadIdx.x & 31;
    int b = g & 16383, c = g >> 14;
    float h = g_h0[(size_t)b * 512 + c * 32 + lane];
    float m = 0.f;
    for (int t = 0; t < NSTEP; t++) {
        m = 0.85f * m + h;
        bool p = m > 1.0f;
        unsigned bits = __ballot_sync(0xFFFFFFFFu, p);
        if (p) m = 0.f;
        if (lane == 0) g_bits0[((size_t)t * 16 + c) * 16384 + b] = bits;
    }
}

// ============================================================
// layer-0 drive: h0 = relu_concat(inputs) @ W0 (fp32, runs once)
// ============================================================
__global__ __launch_bounds__(256)
void gemm0_kernel(const float* __restrict__ Aext, const float* __restrict__ W) {
    constexpr int KT = 8, NK = 256 / KT;
    __shared__ float As[2][KT][128];
    __shared__ float Bs[2][KT][128];
    const int row0 = blockIdx.x * 128, col0 = blockIdx.y * 128;
    const int tid = threadIdx.x;
    const int tx = tid & 15, ty = tid >> 4;
    const int ar = tid >> 1, aq = (tid & 1) * 4;
    const int bk = tid >> 5, bj = (tid & 31) * 4;

    float acc[8][8];
#pragma unroll
    for (int i = 0; i < 8; i++)
#pragma unroll
        for (int j = 0; j < 8; j++) acc[i][j] = 0.f;

    float4 ra, rb;
    auto LOADG = [&](int k0) {
        int kk = k0 + aq;
        if (kk < 128) {
            float4 v = *(const float4*)(Aext + (size_t)(row0 + ar) * 128 + kk);
            ra.x = fmaxf(v.x, 0.f); ra.y = fmaxf(v.y, 0.f);
            ra.z = fmaxf(v.z, 0.f); ra.w = fmaxf(v.w, 0.f);
        } else {
            float4 v = *(const float4*)(Aext + (size_t)(row0 + ar) * 128 + (kk - 128));
            ra.x = fmaxf(-v.x, 0.f); ra.y = fmaxf(-v.y, 0.f);
            ra.z = fmaxf(-v.z, 0.f); ra.w = fmaxf(-v.w, 0.f);
        }
        rb = *(const float4*)(W + (size_t)(k0 + bk) * 512 + col0 + bj);
    };
    auto STORES = [&](int buf) {
        As[buf][aq + 0][ar] = ra.x; As[buf][aq + 1][ar] = ra.y;
        As[buf][aq + 2][ar] = ra.z; As[buf][aq + 3][ar] = ra.w;
        *(float4*)&Bs[buf][bk][bj] = rb;
    };

    LOADG(0); STORES(0); __syncthreads();
    for (int kt = 0; kt < NK; kt++) {
        const int buf = kt & 1;
        if (kt + 1 < NK) LOADG((kt + 1) * KT);
#pragma unroll
        for (int k = 0; k < KT; k++) {
            float4 a0 = *(const float4*)&As[buf][k][ty * 8];
            float4 a1 = *(const float4*)&As[buf][k][ty * 8 + 4];
            float4 b0 = *(const float4*)&Bs[buf][k][tx * 8];
            float4 b1 = *(const float4*)&Bs[buf][k][tx * 8 + 4];
            float av[8] = {a0.x, a0.y, a0.z, a0.w, a1.x, a1.y, a1.z, a1.w};
            float bv[8] = {b0.x, b0.y, b0.z, b0.w, b1.x, b1.y, b1.z, b1.w};
#pragma unroll
            for (int i = 0; i < 8; i++)
#pragma unroll
                for (int j = 0; j < 8; j++) acc[i][j] = fmaf(av[i], bv[j], acc[i][j]);
        }
        if (kt + 1 < NK) STORES(buf ^ 1);
        __syncthreads();
    }
    const int r0 = row0 + ty * 8, c0 = col0 + tx * 8;
#pragma unroll
    for (int i = 0; i < 8; i++) {
        size_t base = (size_t)(r0 + i) * 512 + c0;
        *(float4*)&g_h0[base]     = make_float4(acc[i][0], acc[i][1], acc[i][2], acc[i][3]);
        *(float4*)&g_h0[base + 4] = make_float4(acc[i][4], acc[i][5], acc[i][6], acc[i][7]);
    }
}

// ============================================================
// HMMA GEMM + fused LIF epilogue. A from bit-packed spikes.
// Tile M=128 x N=128; K=512 in 16 chunks of 32; 2 fp16 W-splits.
// B: 3-stage cp.async (16KB/stage); A: bits -> fp16 panel, double-buffered.
// 8 warps, warp tile 64x32: warp_m = wid&1, warp_n = wid>>1.
// MODE 1: A = g_bits0[t]; epi: s1/m1 LIF, spike bits -> g_bits1
// MODE 2: A = g_bits1;    epi: s2/m2 LIF (m2 = out)
// ============================================================
template <int MODE>
__global__ __launch_bounds__(256, 2)
void gemm_mma(int t, float* __restrict__ Mext) {
    extern __shared__ char smem[];
    const int tid = threadIdx.x;
    const int wid = tid >> 5, lane = tid & 31;
    const int warp_m = wid & 1, warp_n = wid >> 1;
    const int row0 = blockIdx.x * 128, col0 = blockIdx.y * 128;
    const uint32_t sb = smem_to_u32(smem);

    const __half* W = (MODE == 1) ? &g_W1t[0][0] : &g_W2t[0][0];
    const uint32_t* bt = (MODE == 1)
        ? g_bits0 + ((size_t)t * 16) * 16384 + row0
        : g_bits1 + row0;

    auto load_B = [&](int c) {
        const uint32_t bp = sb + SMEM_B + (c % 3) * 16384;
        const int k0 = c * 32;
#pragma unroll
        for (int j = 0; j < 4; j++) {
            int i = tid + j * 256;
            int sp = i >> 9, rem = i & 511;
            int n = rem >> 2, q = rem & 3;
            cp16(bp + sp * 8192 + SWZ64(n * 64 + q * 16),
                 W + (size_t)sp * 262144 + (size_t)(col0 + n) * 512 + k0 + q * 8);
        }
        CP_COMMIT();
    };

    // bits -> fp16 0/1 panel (c&1), SW64; 2 threads per row
    auto decode_A = [&](int c) {
        const int r = tid >> 1, hsel = tid & 1;
        const uint32_t w = bt[(size_t)c * 16384 + r];
        const uint32_t pan = sb + (c & 1) * 8192;
#pragma unroll
        for (int qq = 0; qq < 2; qq++) {
            const int q = hsel * 2 + qq;
            uint32_t h2[4];
#pragma unroll
            for (int i = 0; i < 4; i++) {
                uint32_t x = (w >> (q * 8 + i * 2)) & 3u;
                h2[i] = (x & 1u) * 0x3C00u + (x >> 1) * 0x3C000000u;
            }
            asm volatile("st.shared.v4.b32 [%0], {%1,%2,%3,%4};"
                         :: "r"(pan + SWZ64((uint32_t)(r * 64 + q * 16))),
                            "r"(h2[0]), "r"(h2[1]), "r"(h2[2]), "r"(h2[3]));
        }
    };

    float acc[4][4][4];
#pragma unroll
    for (int mt = 0; mt < 4; mt++)
#pragma unroll
        for (int nb = 0; nb < 4; nb++)
#pragma unroll
            for (int e = 0; e < 4; e++) acc[mt][nb][e] = 0.f;

    const int mat = lane >> 3, mrr = lane & 7;

    load_B(0);
    load_B(1);
    decode_A(0);
    __syncthreads();          // panel 0 visible before first mainloop pass

#pragma unroll 1
    for (int c = 0; c < 16; c++) {
        if (c < 15) CP_WAIT(1); else CP_WAIT(0);
        __syncthreads();
        if (c + 2 < 16) load_B(c + 2);
        if (c + 1 < 16) decode_A(c + 1);

        const uint32_t ab = sb + (c & 1) * 8192;
        const uint32_t bb = sb + SMEM_B + (c % 3) * 16384;
#pragma unroll
        for (int k16 = 0; k16 < 2; k16++) {
            const int k0 = k16 * 16;
            uint32_t a[4][4];
#pragma unroll
            for (int mt = 0; mt < 4; mt++) {
                int row = warp_m * 64 + mt * 16 + (mat & 1) * 8 + mrr;
                int kk  = k0 + (mat >> 1) * 8;
                ldm4(a[mt][0], a[mt][1], a[mt][2], a[mt][3],
                     ab + SWZ64((uint32_t)(row * 64 + kk * 2)));
            }
#pragma unroll
            for (int sp = 0; sp < 2; sp++) {
                uint32_t b[2][4];
#pragma unroll
                for (int n2 = 0; n2 < 2; n2++) {
                    int n  = warp_n * 32 + n2 * 16 + (mat >> 1) * 8 + mrr;
                    int kk = k0 + (mat & 1) * 8;
                    ldm4(b[n2][0], b[n2][1], b[n2][2], b[n2][3],
                         bb + sp * 8192 + SWZ64((uint32_t)(n * 64 + kk * 2)));
                }
#pragma unroll
                for (int mt = 0; mt < 4; mt++)
#pragma unroll
                    for (int nb = 0; nb < 4; nb++)
                        mma16816(acc[mt][nb], a[mt],
                                 b[nb >> 1][(nb & 1) * 2],
                                 b[nb >> 1][(nb & 1) * 2 + 1]);
            }
        }
        __syncthreads();
    }

    // ---- fused LIF epilogue (register-direct) ----
    const int er = row0 + warp_m * 64 + (lane >> 2);
    const int ec = col0 + warp_n * 32 + (lane & 3) * 2;
    if (MODE == 1) {
        const int word = blockIdx.y * 4 + warp_n;
#pragma unroll
        for (int mt = 0; mt < 4; mt++)
#pragma unroll
            for (int hrow = 0; hrow < 2; hrow++) {
                const int r = er + mt * 16 + hrow * 8;
                uint32_t pb = 0;
#pragma unroll
                for (int nb = 0; nb < 4; nb++) {
                    size_t ix = (size_t)r * 512 + ec + nb * 8;
                    float2 sv = *(const float2*)(g_s1 + ix);
                    float2 mv = *(const float2*)(g_m1 + ix);
                    sv.x = 0.9f * sv.x + acc[mt][nb][hrow * 2 + 0];
                    mv.x = 0.85f * mv.x + sv.x;
                    sv.y = 0.9f * sv.y + acc[mt][nb][hrow * 2 + 1];
                    mv.y = 0.85f * mv.y + sv.y;
                    uint32_t b0 = (mv.x > 1.f) ? 1u : 0u;
                    uint32_t b1 = (mv.y > 1.f) ? 1u : 0u;
                    if (mv.x > 1.f) mv.x = 0.f;
                    if (mv.y > 1.f) mv.y = 0.f;
                    pb |= (b0 | (b1 << 1)) << (nb * 8 + (lane & 3) * 2);
                    *(float2*)(g_s1 + ix) = sv;
                    *(float2*)(g_m1 + ix) = mv;
                }
                pb |= __shfl_xor_sync(0xFFFFFFFFu, pb, 1);
                pb |= __shfl_xor_sync(0xFFFFFFFFu, pb, 2);
                if ((lane & 3) == 0) g_bits1[word * 16384 + r] = pb;
            }
    } else {
#pragma unroll
        for (int mt = 0; mt < 4; mt++)
#pragma unroll
            for (int hrow = 0; hrow < 2; hrow++) {
                const int r = er + mt * 16 + hrow * 8;
#pragma unroll
                for (int nb = 0; nb < 4; nb++) {
                    size_t ix = (size_t)r * 512 + ec + nb * 8;
                    float2 sv = *(const float2*)(g_s2 + ix);
                    float2 mv = *(const float2*)(Mext + ix);
                    sv.x = 0.9f * sv.x + acc[mt][nb][hrow * 2 + 0];
                    mv.x = 0.85f * mv.x + sv.x;
                    sv.y = 0.9f * sv.y + acc[mt][nb][hrow * 2 + 1];
                    mv.y = 0.85f * mv.y + sv.y;
                    *(float2*)(g_s2 + ix) = sv;
                    *(float2*)(Mext + ix) = mv;
                }
            }
    }
}

// ============================================================
// launch
// ============================================================
extern "C" void kernel_launch(void* const* d_in, const int* in_sizes, int n_in,
                              void* d_out, int out_size) {
    (void)in_sizes; (void)n_in; (void)out_size;
    const float* inp = (const float*)d_in[0];   // [16384, 128]
    const float* W0  = (const float*)d_in[1];   // [256, 512]
    const float* W1  = (const float*)d_in[2];   // [512, 512]
    const float* W2  = (const float*)d_in[3];   // [512, 512]
    float* out = (float*)d_out;                 // m2 state [16384, 512]

    cudaFuncSetAttribute(gemm_mma<1>, cudaFuncAttributeMaxDynamicSharedMemorySize, SMEM_TOT);
    cudaFuncSetAttribute(gemm_mma<2>, cudaFuncAttributeMaxDynamicSharedMemorySize, SMEM_TOT);

    zero_kernel<<<(NELEM / 4) / 256, 256>>>((float4*)out);
    prep_kernel<1><<<1024, 256>>>(W1);
    prep_kernel<2><<<1024, 256>>>(W2);
    gemm0_kernel<<<dim3(128, 4), 256>>>(inp, W0);
    spikes0_kernel<<<32768, 256>>>();

    dim3 grid(128, 4);
    for (int t = 0; t < NSTEP; t++) {
        gemm_mma<1><<<grid, 256, SMEM_TOT>>>(t, nullptr);
        gemm_mma<2><<<grid, 256, SMEM_TOT>>>(0, out);
    }
}

// round 10
// speedup vs baseline: 1.8382x; 1.4114x over previous
#include <cuda_runtime.h>
#include <cuda_fp16.h>
#include <cstdint>

// ============================================================
// 3-layer SNN. B=16384, H=512, 127 steps.
// R10 = R7 GEMM mainloop (proven fastest) + structural overlap:
//  - layer-0 spikes precomputed for ALL t as fp16 (m0 recurrence is
//    input-only) -> gemm1(t+1) independent of gemm2(t)
//  - spk1 double-buffered (parity t&1)
//  - gemm2(t) runs on a forked stream; events express g1(t)->g2(t) and
//    g2(t)->g1(t+2). gemm1(t+1) fills gemm2(t)'s wave tail -> kills the
//    512/296 wave-quantization loss (~13%) and launch gaps.
// Engine: mma.sync m16n8k16 fp16, 2 exact fp16 W-splits, fp32 accum
// (identical MMA order to R7 -> expect bit-identical rel_err).
// ============================================================

constexpr int NSTEP = 127;
constexpr int NELEM = 16384 * 512;

__device__ float g_h0[NELEM];
__device__ float g_s1[NELEM];
__device__ float g_m1[NELEM];
__device__ float g_s2[NELEM];
__device__ __half g_spk0all[(size_t)NSTEP * NELEM];   // 2.13GB (< 2^31 bytes)
__device__ __half g_spk1a[NELEM];                     // spk1 parity 0
__device__ __half g_spk1b[NELEM];                     // spk1 parity 1
__device__ __half g_W1t[2][512 * 512];   // [split][N][K] K-contiguous
__device__ __half g_W2t[2][512 * 512];

// ---- PTX helpers (sm_80-class, valid at sm_103 base target) ----
__device__ __forceinline__ uint32_t smem_to_u32(const void* p) {
    uint32_t a;
    asm("{ .reg .u64 t; cvta.to.shared.u64 t, %1; cvt.u32.u64 %0, t; }"
        : "=r"(a) : "l"(p));
    return a;
}
__device__ __forceinline__ void cp16(uint32_t dst, const void* src) {
    asm volatile("cp.async.cg.shared.global [%0], [%1], 16;"
                 :: "r"(dst), "l"(src) : "memory");
}
#define CP_COMMIT() asm volatile("cp.async.commit_group;" ::: "memory")
#define CP_WAIT(N)  asm volatile("cp.async.wait_group %0;" :: "n"(N) : "memory")

__device__ __forceinline__ void ldm4(uint32_t& r0, uint32_t& r1, uint32_t& r2,
                                     uint32_t& r3, uint32_t addr) {
    asm volatile("ldmatrix.sync.aligned.m8n8.x4.shared.b16 {%0,%1,%2,%3}, [%4];"
                 : "=r"(r0), "=r"(r1), "=r"(r2), "=r"(r3) : "r"(addr));
}
__device__ __forceinline__ void mma16816(float* c, const uint32_t* a,
                                         uint32_t b0, uint32_t b1) {
    asm volatile(
        "mma.sync.aligned.m16n8k16.row.col.f32.f16.f16.f32 "
        "{%0,%1,%2,%3}, {%4,%5,%6,%7}, {%8,%9}, {%0,%1,%2,%3};"
        : "+f"(c[0]), "+f"(c[1]), "+f"(c[2]), "+f"(c[3])
        : "r"(a[0]), "r"(a[1]), "r"(a[2]), "r"(a[3]), "r"(b0), "r"(b1));
}
#define SWZ64(x) ((x) ^ (((x) >> 3) & 0x30))

// ============================================================
// one-time kernels
// ============================================================
__global__ void zero_kernel(float4* __restrict__ out) {
    int i = blockIdx.x * blockDim.x + threadIdx.x;
    float4 z = make_float4(0.f, 0.f, 0.f, 0.f);
    ((float4*)g_s1)[i] = z;
    ((float4*)g_m1)[i] = z;
    ((float4*)g_s2)[i] = z;
    out[i] = z;
}

// exact 2-way fp16 split + transpose of W [512K x 512N] -> Wt[2][N][K]
template <int WHICH>
__global__ void prep_kernel(const float* __restrict__ Wsrc) {
    int idx = blockIdx.x * blockDim.x + threadIdx.x;  // over 512*512
    int k = idx >> 9, n = idx & 511;
    float w = Wsrc[idx];
    __half hi = __float2half_rn(w);
    __half lo = __float2half_rn(w - __half2float(hi));
    __half (*dst)[512 * 512] = (WHICH == 1) ? g_W1t : g_W2t;
    int t = n * 512 + k;
    dst[0][t] = hi;
    dst[1][t] = lo;
}

// layer-0 LIF trajectories for all timesteps -> fp16 spikes (coalesced per t)
__global__ void spikes0_kernel() {
    int idx = blockIdx.x * blockDim.x + threadIdx.x;  // over NELEM
    float h = g_h0[idx];
    float m = 0.f;
#pragma unroll 1
    for (int t = 0; t < NSTEP; t++) {
        m = 0.85f * m + h;
        bool p = m > 1.0f;
        g_spk0all[(size_t)t * NELEM + idx] = p ? __float2half(1.f)
                                               : __float2half(0.f);
        if (p) m = 0.f;
    }
}

// ============================================================
// layer-0 drive: h0 = relu_concat(inputs) @ W0 (fp32, runs once)
// ============================================================
__global__ __launch_bounds__(256)
void gemm0_kernel(const float* __restrict__ Aext, const float* __restrict__ W) {
    constexpr int KT = 8, NK = 256 / KT;
    __shared__ float As[2][KT][128];
    __shared__ float Bs[2][KT][128];
    const int row0 = blockIdx.x * 128, col0 = blockIdx.y * 128;
    const int tid = threadIdx.x;
    const int tx = tid & 15, ty = tid >> 4;
    const int ar = tid >> 1, aq = (tid & 1) * 4;
    const int bk = tid >> 5, bj = (tid & 31) * 4;

    float acc[8][8];
#pragma unroll
    for (int i = 0; i < 8; i++)
#pragma unroll
        for (int j = 0; j < 8; j++) acc[i][j] = 0.f;

    float4 ra, rb;
    auto LOADG = [&](int k0) {
        int kk = k0 + aq;
        if (kk < 128) {
            float4 v = *(const float4*)(Aext + (size_t)(row0 + ar) * 128 + kk);
            ra.x = fmaxf(v.x, 0.f); ra.y = fmaxf(v.y, 0.f);
            ra.z = fmaxf(v.z, 0.f); ra.w = fmaxf(v.w, 0.f);
        } else {
            float4 v = *(const float4*)(Aext + (size_t)(row0 + ar) * 128 + (kk - 128));
            ra.x = fmaxf(-v.x, 0.f); ra.y = fmaxf(-v.y, 0.f);
            ra.z = fmaxf(-v.z, 0.f); ra.w = fmaxf(-v.w, 0.f);
        }
        rb = *(const float4*)(W + (size_t)(k0 + bk) * 512 + col0 + bj);
    };
    auto STORES = [&](int buf) {
        As[buf][aq + 0][ar] = ra.x; As[buf][aq + 1][ar] = ra.y;
        As[buf][aq + 2][ar] = ra.z; As[buf][aq + 3][ar] = ra.w;
        *(float4*)&Bs[buf][bk][bj] = rb;
    };

    LOADG(0); STORES(0); __syncthreads();
    for (int kt = 0; kt < NK; kt++) {
        const int buf = kt & 1;
        if (kt + 1 < NK) LOADG((kt + 1) * KT);
#pragma unroll
        for (int k = 0; k < KT; k++) {
            float4 a0 = *(const float4*)&As[buf][k][ty * 8];
            float4 a1 = *(const float4*)&As[buf][k][ty * 8 + 4];
            float4 b0 = *(const float4*)&Bs[buf][k][tx * 8];
            float4 b1 = *(const float4*)&Bs[buf][k][tx * 8 + 4];
            float av[8] = {a0.x, a0.y, a0.z, a0.w, a1.x, a1.y, a1.z, a1.w};
            float bv[8] = {b0.x, b0.y, b0.z, b0.w, b1.x, b1.y, b1.z, b1.w};
#pragma unroll
            for (int i = 0; i < 8; i++)
#pragma unroll
                for (int j = 0; j < 8; j++) acc[i][j] = fmaf(av[i], bv[j], acc[i][j]);
        }
        if (kt + 1 < NK) STORES(buf ^ 1);
        __syncthreads();
    }
    const int r0 = row0 + ty * 8, c0 = col0 + tx * 8;
#pragma unroll
    for (int i = 0; i < 8; i++) {
        size_t base = (size_t)(r0 + i) * 512 + c0;
        *(float4*)&g_h0[base]     = make_float4(acc[i][0], acc[i][1], acc[i][2], acc[i][3]);
        *(float4*)&g_h0[base + 4] = make_float4(acc[i][4], acc[i][5], acc[i][6], acc[i][7]);
    }
}

// ============================================================
// HMMA GEMM + fused LIF epilogue (R7 mainloop, A/spk pointers as args)
// Tile M=128 x N=128; K=512 in 16 chunks of 32; 2 fp16 W-splits.
// 3-stage cp.async pipeline, 24KB/stage; SW64; warp tile 64x32.
// MODE 1: epi s1/m1 LIF + spike -> spk_out fp16 ; MODE 2: epi s2/m2 (m2=out)
// ============================================================
constexpr int STAGE_BYTES = 24576;
constexpr int SMEM_NEED   = 3 * STAGE_BYTES;   // 72KB -> 2 CTAs/SM

template <int MODE>
__global__ __launch_bounds__(256, 2)
void gemm_mma(const __half* __restrict__ A, __half* __restrict__ spk_out,
              float* __restrict__ Mext) {
    extern __shared__ char smem[];
    const int tid = threadIdx.x;
    const int wid = tid >> 5, lane = tid & 31;
    const int warp_m = wid & 1, warp_n = wid >> 1;
    const int row0 = blockIdx.x * 128, col0 = blockIdx.y * 128;

    const __half* W = (MODE == 1) ? &g_W1t[0][0] : &g_W2t[0][0];
    const uint32_t sb = smem_to_u32(smem);

    auto load_chunk = [&](int c, int s) {
        const uint32_t ap = sb + s * STAGE_BYTES;
        const uint32_t bp = ap + 8192;
        const int k0 = c * 32;
#pragma unroll
        for (int j = 0; j < 2; j++) {                  // A: 512 x 16B
            int i = tid + j * 256;
            int r = i >> 2, q = i & 3;
            cp16(ap + SWZ64(r * 64 + q * 16),
                 A + (size_t)(row0 + r) * 512 + k0 + q * 8);
        }
#pragma unroll
        for (int j = 0; j < 4; j++) {                  // B: 2 x 512 x 16B
            int i = tid + j * 256;
            int sp = i >> 9, rem = i & 511;
            int n = rem >> 2, q = rem & 3;
            cp16(bp + sp * 8192 + SWZ64(n * 64 + q * 16),
                 W + (size_t)sp * 262144 + (size_t)(col0 + n) * 512 + k0 + q * 8);
        }
        CP_COMMIT();
    };

    load_chunk(0, 0);
    load_chunk(1, 1);

    float acc[4][4][4];
#pragma unroll
    for (int mt = 0; mt < 4; mt++)
#pragma unroll
        for (int nb = 0; nb < 4; nb++)
#pragma unroll
            for (int e = 0; e < 4; e++) acc[mt][nb][e] = 0.f;

    const int mat = lane >> 3, mrr = lane & 7;

#pragma unroll 1
    for (int c = 0; c < 16; c++) {
        const int s = c % 3;
        if (c < 15) CP_WAIT(1); else CP_WAIT(0);
        __syncthreads();
        if (c + 2 < 16) load_chunk(c + 2, (c + 2) % 3);

        const uint32_t ab = sb + s * STAGE_BYTES;
        const uint32_t bb = ab + 8192;
#pragma unroll
        for (int k16 = 0; k16 < 2; k16++) {
            const int k0 = k16 * 16;
            uint32_t a[4][4];
#pragma unroll
            for (int mt = 0; mt < 4; mt++) {
                int row = warp_m * 64 + mt * 16 + (mat & 1) * 8 + mrr;
                int kk  = k0 + (mat >> 1) * 8;
                ldm4(a[mt][0], a[mt][1], a[mt][2], a[mt][3],
                     ab + SWZ64(row * 64 + kk * 2));
            }
#pragma unroll
            for (int sp = 0; sp < 2; sp++) {
                uint32_t b[2][4];
#pragma unroll
                for (int n2 = 0; n2 < 2; n2++) {
                    int n  = warp_n * 32 + n2 * 16 + (mat >> 1) * 8 + mrr;
                    int kk = k0 + (mat & 1) * 8;
                    ldm4(b[n2][0], b[n2][1], b[n2][2], b[n2][3],
                         bb + sp * 8192 + SWZ64(n * 64 + kk * 2));
                }
#pragma unroll
                for (int mt = 0; mt < 4; mt++)
#pragma unroll
                    for (int nb = 0; nb < 4; nb++)
                        mma16816(acc[mt][nb], a[mt],
                                 b[nb >> 1][(nb & 1) * 2],
                                 b[nb >> 1][(nb & 1) * 2 + 1]);
            }
        }
        __syncthreads();
    }

    // ---- fused LIF epilogue, direct from mma fragments ----
    float* S = (MODE == 1) ? g_s1 : g_s2;
    float* M = (MODE == 1) ? g_m1 : Mext;
    const int er = row0 + warp_m * 64 + (lane >> 2);
    const int ec = col0 + warp_n * 32 + (lane & 3) * 2;
#pragma unroll
    for (int mt = 0; mt < 4; mt++)
#pragma unroll
        for (int nb = 0; nb < 4; nb++)
#pragma unroll
            for (int hrow = 0; hrow < 2; hrow++) {
                size_t ix = (size_t)(er + mt * 16 + hrow * 8) * 512 + ec + nb * 8;
                float2 sv = *(const float2*)(S + ix);
                float2 mv = *(const float2*)(M + ix);
                float hx = acc[mt][nb][hrow * 2 + 0];
                float hy = acc[mt][nb][hrow * 2 + 1];
                sv.x = 0.9f * sv.x + hx;  mv.x = 0.85f * mv.x + sv.x;
                sv.y = 0.9f * sv.y + hy;  mv.y = 0.85f * mv.y + sv.y;
                if (MODE == 1) {
                    float px = (mv.x > 1.f) ? 1.f : 0.f;  mv.x = (mv.x > 1.f) ? 0.f : mv.x;
                    float py = (mv.y > 1.f) ? 1.f : 0.f;  mv.y = (mv.y > 1.f) ? 0.f : mv.y;
                    *(__half2*)(spk_out + ix) = __floats2half2_rn(px, py);
                }
                *(float2*)(S + ix) = sv;
                *(float2*)(M + ix) = mv;
            }
}

// ============================================================
// launch — forked-stream pipeline:
//   S (default per-thread): g1(0), g1(1), [w e2] g1(2), ...
//   S2:                     [w e1] g2(0), [w e1] g2(1), ...
// g2(t) waits g1(t) (e1[t&1]); g1(t+2) waits g2(t) (e2[t&1]).
// ============================================================
extern "C" void kernel_launch(void* const* d_in, const int* in_sizes, int n_in,
                              void* d_out, int out_size) {
    (void)in_sizes; (void)n_in; (void)out_size;
    const float* inp = (const float*)d_in[0];   // [16384, 128]
    const float* W0  = (const float*)d_in[1];   // [256, 512]
    const float* W1  = (const float*)d_in[2];   // [512, 512]
    const float* W2  = (const float*)d_in[3];   // [512, 512]
    float* out = (float*)d_out;                 // m2 state [16384, 512]

    static cudaStream_t s2 = nullptr;
    static cudaEvent_t e1[2], e2[2];
    if (s2 == nullptr) {                         // host-side handles only;
        cudaStreamCreateWithFlags(&s2, cudaStreamNonBlocking);
        for (int i = 0; i < 2; i++) {
            cudaEventCreateWithFlags(&e1[i], cudaEventDisableTiming);
            cudaEventCreateWithFlags(&e2[i], cudaEventDisableTiming);
        }
        cudaFuncSetAttribute(gemm_mma<1>,
                             cudaFuncAttributeMaxDynamicSharedMemorySize, SMEM_NEED);
        cudaFuncSetAttribute(gemm_mma<2>,
                             cudaFuncAttributeMaxDynamicSharedMemorySize, SMEM_NEED);
    }

    __half* d_spk0all;  cudaGetSymbolAddress((void**)&d_spk0all, g_spk0all);
    __half* d_spk1a;    cudaGetSymbolAddress((void**)&d_spk1a, g_spk1a);
    __half* d_spk1b;    cudaGetSymbolAddress((void**)&d_spk1b, g_spk1b);
    __half* spk1buf[2] = {d_spk1a, d_spk1b};

    zero_kernel<<<(NELEM / 4) / 256, 256>>>((float4*)out);
    prep_kernel<1><<<1024, 256>>>(W1);
    prep_kernel<2><<<1024, 256>>>(W2);
    gemm0_kernel<<<dim3(128, 4), 256>>>(inp, W0);
    spikes0_kernel<<<NELEM / 256, 256>>>();

    dim3 grid(128, 4);
    for (int t = 0; t < NSTEP; t++) {
        const int par = t & 1;
        if (t >= 2)
            cudaStreamWaitEvent(cudaStreamPerThread, e2[par], 0);
        gemm_mma<1><<<grid, 256, SMEM_NEED>>>(
            d_spk0all + (size_t)t * NELEM, spk1buf[par], nullptr);
        cudaEventRecord(e1[par], cudaStreamPerThread);
        cudaStreamWaitEvent(s2, e1[par], 0);
        gemm_mma<2><<<grid, 256, SMEM_NEED, s2>>>(spk1buf[par], nullptr, out);
        cudaEventRecord(e2[par], s2);
    }
    // join forked stream back before capture ends
    cudaStreamWaitEvent(cudaStreamPerThread, e2[0], 0);
    cudaStreamWaitEvent(cudaStreamPerThread, e2[1], 0);
}

// round 11
// speedup vs baseline: 1.8929x; 1.0298x over previous
#include <cuda_runtime.h>
#include <cuda_fp16.h>
#include <cstdint>

// ============================================================
// 3-layer SNN. B=16384, H=512, 127 steps.
// R11 = R10 (forked-stream overlap, spk0 precomputed fp16, double-buffered
// spk1, R7 HMMA mainloop) +
//  - trailing per-chunk __syncthreads removed (leading barrier alone gives
//    the WAR guarantee with >=3 stages)
//  - 4-stage cp.async pipeline, prefetch depth 3, wait_group(2)
// Engine: mma.sync m16n8k16 fp16, 2 exact fp16 W-splits, fp32 accum
// (identical MMA order -> expect bit-identical rel_err 1.011837e-4).
// ============================================================

constexpr int NSTEP = 127;
constexpr int NELEM = 16384 * 512;

__device__ float g_h0[NELEM];
__device__ float g_s1[NELEM];
__device__ float g_m1[NELEM];
__device__ float g_s2[NELEM];
__device__ __half g_spk0all[(size_t)NSTEP * NELEM];   // 2.13GB
__device__ __half g_spk1a[NELEM];
__device__ __half g_spk1b[NELEM];
__device__ __half g_W1t[2][512 * 512];   // [split][N][K] K-contiguous
__device__ __half g_W2t[2][512 * 512];

// ---- PTX helpers (sm_80-class, valid at sm_103 base target) ----
__device__ __forceinline__ uint32_t smem_to_u32(const void* p) {
    uint32_t a;
    asm("{ .reg .u64 t; cvta.to.shared.u64 t, %1; cvt.u32.u64 %0, t; }"
        : "=r"(a) : "l"(p));
    return a;
}
__device__ __forceinline__ void cp16(uint32_t dst, const void* src) {
    asm volatile("cp.async.cg.shared.global [%0], [%1], 16;"
                 :: "r"(dst), "l"(src) : "memory");
}
#define CP_COMMIT() asm volatile("cp.async.commit_group;" ::: "memory")
#define CP_WAIT(N)  asm volatile("cp.async.wait_group %0;" :: "n"(N) : "memory")

__device__ __forceinline__ void ldm4(uint32_t& r0, uint32_t& r1, uint32_t& r2,
                                     uint32_t& r3, uint32_t addr) {
    asm volatile("ldmatrix.sync.aligned.m8n8.x4.shared.b16 {%0,%1,%2,%3}, [%4];"
                 : "=r"(r0), "=r"(r1), "=r"(r2), "=r"(r3) : "r"(addr));
}
__device__ __forceinline__ void mma16816(float* c, const uint32_t* a,
                                         uint32_t b0, uint32_t b1) {
    asm volatile(
        "mma.sync.aligned.m16n8k16.row.col.f32.f16.f16.f32 "
        "{%0,%1,%2,%3}, {%4,%5,%6,%7}, {%8,%9}, {%0,%1,%2,%3};"
        : "+f"(c[0]), "+f"(c[1]), "+f"(c[2]), "+f"(c[3])
        : "r"(a[0]), "r"(a[1]), "r"(a[2]), "r"(a[3]), "r"(b0), "r"(b1));
}
#define SWZ64(x) ((x) ^ (((x) >> 3) & 0x30))

// ============================================================
// one-time kernels
// ============================================================
__global__ void zero_kernel(float4* __restrict__ out) {
    int i = blockIdx.x * blockDim.x + threadIdx.x;
    float4 z = make_float4(0.f, 0.f, 0.f, 0.f);
    ((float4*)g_s1)[i] = z;
    ((float4*)g_m1)[i] = z;
    ((float4*)g_s2)[i] = z;
    out[i] = z;
}

// exact 2-way fp16 split + transpose of W [512K x 512N] -> Wt[2][N][K]
template <int WHICH>
__global__ void prep_kernel(const float* __restrict__ Wsrc) {
    int idx = blockIdx.x * blockDim.x + threadIdx.x;  // over 512*512
    int k = idx >> 9, n = idx & 511;
    float w = Wsrc[idx];
    __half hi = __float2half_rn(w);
    __half lo = __float2half_rn(w - __half2float(hi));
    __half (*dst)[512 * 512] = (WHICH == 1) ? g_W1t : g_W2t;
    int t = n * 512 + k;
    dst[0][t] = hi;
    dst[1][t] = lo;
}

// layer-0 LIF trajectories for all timesteps -> fp16 spikes
__global__ void spikes0_kernel() {
    int idx = blockIdx.x * blockDim.x + threadIdx.x;  // over NELEM
    float h = g_h0[idx];
    float m = 0.f;
#pragma unroll 1
    for (int t = 0; t < NSTEP; t++) {
        m = 0.85f * m + h;
        bool p = m > 1.0f;
        g_spk0all[(size_t)t * NELEM + idx] = p ? __float2half(1.f)
                                               : __float2half(0.f);
        if (p) m = 0.f;
    }
}

// ============================================================
// layer-0 drive: h0 = relu_concat(inputs) @ W0 (fp32, runs once)
// ============================================================
__global__ __launch_bounds__(256)
void gemm0_kernel(const float* __restrict__ Aext, const float* __restrict__ W) {
    constexpr int KT = 8, NK = 256 / KT;
    __shared__ float As[2][KT][128];
    __shared__ float Bs[2][KT][128];
    const int row0 = blockIdx.x * 128, col0 = blockIdx.y * 128;
    const int tid = threadIdx.x;
    const int tx = tid & 15, ty = tid >> 4;
    const int ar = tid >> 1, aq = (tid & 1) * 4;
    const int bk = tid >> 5, bj = (tid & 31) * 4;

    float acc[8][8];
#pragma unroll
    for (int i = 0; i < 8; i++)
#pragma unroll
        for (int j = 0; j < 8; j++) acc[i][j] = 0.f;

    float4 ra, rb;
    auto LOADG = [&](int k0) {
        int kk = k0 + aq;
        if (kk < 128) {
            float4 v = *(const float4*)(Aext + (size_t)(row0 + ar) * 128 + kk);
            ra.x = fmaxf(v.x, 0.f); ra.y = fmaxf(v.y, 0.f);
            ra.z = fmaxf(v.z, 0.f); ra.w = fmaxf(v.w, 0.f);
        } else {
            float4 v = *(const float4*)(Aext + (size_t)(row0 + ar) * 128 + (kk - 128));
            ra.x = fmaxf(-v.x, 0.f); ra.y = fmaxf(-v.y, 0.f);
            ra.z = fmaxf(-v.z, 0.f); ra.w = fmaxf(-v.w, 0.f);
        }
        rb = *(const float4*)(W + (size_t)(k0 + bk) * 512 + col0 + bj);
    };
    auto STORES = [&](int buf) {
        As[buf][aq + 0][ar] = ra.x; As[buf][aq + 1][ar] = ra.y;
        As[buf][aq + 2][ar] = ra.z; As[buf][aq + 3][ar] = ra.w;
        *(float4*)&Bs[buf][bk][bj] = rb;
    };

    LOADG(0); STORES(0); __syncthreads();
    for (int kt = 0; kt < NK; kt++) {
        const int buf = kt & 1;
        if (kt + 1 < NK) LOADG((kt + 1) * KT);
#pragma unroll
        for (int k = 0; k < KT; k++) {
            float4 a0 = *(const float4*)&As[buf][k][ty * 8];
            float4 a1 = *(const float4*)&As[buf][k][ty * 8 + 4];
            float4 b0 = *(const float4*)&Bs[buf][k][tx * 8];
            float4 b1 = *(const float4*)&Bs[buf][k][tx * 8 + 4];
            float av[8] = {a0.x, a0.y, a0.z, a0.w, a1.x, a1.y, a1.z, a1.w};
            float bv[8] = {b0.x, b0.y, b0.z, b0.w, b1.x, b1.y, b1.z, b1.w};
#pragma unroll
            for (int i = 0; i < 8; i++)
#pragma unroll
                for (int j = 0; j < 8; j++) acc[i][j] = fmaf(av[i], bv[j], acc[i][j]);
        }
        if (kt + 1 < NK) STORES(buf ^ 1);
        __syncthreads();
    }
    const int r0 = row0 + ty * 8, c0 = col0 + tx * 8;
#pragma unroll
    for (int i = 0; i < 8; i++) {
        size_t base = (size_t)(r0 + i) * 512 + c0;
        *(float4*)&g_h0[base]     = make_float4(acc[i][0], acc[i][1], acc[i][2], acc[i][3]);
        *(float4*)&g_h0[base + 4] = make_float4(acc[i][4], acc[i][5], acc[i][6], acc[i][7]);
    }
}

// ============================================================
// HMMA GEMM + fused LIF epilogue
// Tile M=128 x N=128; K=512 in 16 chunks of 32; 2 fp16 W-splits.
// 4-stage cp.async pipeline (24KB/stage, prefetch depth 3, wait_group 2),
// ONE barrier per chunk. SW64. 8 warps, warp tile 64x32.
// ============================================================
constexpr int STAGE_BYTES = 24576;
constexpr int SMEM_NEED   = 4 * STAGE_BYTES;   // 96KB -> 2 CTAs/SM

template <int MODE>
__global__ __launch_bounds__(256, 2)
void gemm_mma(const __half* __restrict__ A, __half* __restrict__ spk_out,
              float* __restrict__ Mext) {
    extern __shared__ char smem[];
    const int tid = threadIdx.x;
    const int wid = tid >> 5, lane = tid & 31;
    const int warp_m = wid & 1, warp_n = wid >> 1;
    const int row0 = blockIdx.x * 128, col0 = blockIdx.y * 128;

    const __half* W = (MODE == 1) ? &g_W1t[0][0] : &g_W2t[0][0];
    const uint32_t sb = smem_to_u32(smem);

    auto load_chunk = [&](int c, int s) {
        const uint32_t ap = sb + s * STAGE_BYTES;
        const uint32_t bp = ap + 8192;
        const int k0 = c * 32;
#pragma unroll
        for (int j = 0; j < 2; j++) {                  // A: 512 x 16B
            int i = tid + j * 256;
            int r = i >> 2, q = i & 3;
            cp16(ap + SWZ64(r * 64 + q * 16),
                 A + (size_t)(row0 + r) * 512 + k0 + q * 8);
        }
#pragma unroll
        for (int j = 0; j < 4; j++) {                  // B: 2 x 512 x 16B
            int i = tid + j * 256;
            int sp = i >> 9, rem = i & 511;
            int n = rem >> 2, q = rem & 3;
            cp16(bp + sp * 8192 + SWZ64(n * 64 + q * 16),
                 W + (size_t)sp * 262144 + (size_t)(col0 + n) * 512 + k0 + q * 8);
        }
        CP_COMMIT();
    };

    load_chunk(0, 0);
    load_chunk(1, 1);
    load_chunk(2, 2);

    float acc[4][4][4];
#pragma unroll
    for (int mt = 0; mt < 4; mt++)
#pragma unroll
        for (int nb = 0; nb < 4; nb++)
#pragma unroll
            for (int e = 0; e < 4; e++) acc[mt][nb][e] = 0.f;

    const int mat = lane >> 3, mrr = lane & 7;

#pragma unroll 1
    for (int c = 0; c < 16; c++) {
        const int s = c & 3;
        if (c <= 13)      CP_WAIT(2);
        else if (c == 14) CP_WAIT(1);
        else              CP_WAIT(0);
        __syncthreads();                       // single barrier per chunk
        if (c + 3 < 16) load_chunk(c + 3, (c + 3) & 3);

        const uint32_t ab = sb + s * STAGE_BYTES;
        const uint32_t bb = ab + 8192;
#pragma unroll
        for (int k16 = 0; k16 < 2; k16++) {
            const int k0 = k16 * 16;
            uint32_t a[4][4];
#pragma unroll
            for (int mt = 0; mt < 4; mt++) {
                int row = warp_m * 64 + mt * 16 + (mat & 1) * 8 + mrr;
                int kk  = k0 + (mat >> 1) * 8;
                ldm4(a[mt][0], a[mt][1], a[mt][2], a[mt][3],
                     ab + SWZ64(row * 64 + kk * 2));
            }
#pragma unroll
            for (int sp = 0; sp < 2; sp++) {
                uint32_t b[2][4];
#pragma unroll
                for (int n2 = 0; n2 < 2; n2++) {
                    int n  = warp_n * 32 + n2 * 16 + (mat >> 1) * 8 + mrr;
                    int kk = k0 + (mat & 1) * 8;
                    ldm4(b[n2][0], b[n2][1], b[n2][2], b[n2][3],
                         bb + sp * 8192 + SWZ64(n * 64 + kk * 2));
                }
#pragma unroll
                for (int mt = 0; mt < 4; mt++)
#pragma unroll
                    for (int nb = 0; nb < 4; nb++)
                        mma16816(acc[mt][nb], a[mt],
                                 b[nb >> 1][(nb & 1) * 2],
                                 b[nb >> 1][(nb & 1) * 2 + 1]);
            }
        }
        // no trailing barrier: leading barrier of iteration c+1 provides the
        // WAR guarantee (stage (c+4)&3 was last read in iteration c, before
        // every thread's arrival at that barrier)
    }

    // ---- fused LIF epilogue, direct from mma fragments ----
    float* S = (MODE == 1) ? g_s1 : g_s2;
    float* M = (MODE == 1) ? g_m1 : Mext;
    const int er = row0 + warp_m * 64 + (lane >> 2);
    const int ec = col0 + warp_n * 32 + (lane & 3) * 2;
#pragma unroll
    for (int mt = 0; mt < 4; mt++)
#pragma unroll
        for (int nb = 0; nb < 4; nb++)
#pragma unroll
            for (int hrow = 0; hrow < 2; hrow++) {
                size_t ix = (size_t)(er + mt * 16 + hrow * 8) * 512 + ec + nb * 8;
                float2 sv = *(const float2*)(S + ix);
                float2 mv = *(const float2*)(M + ix);
                float hx = acc[mt][nb][hrow * 2 + 0];
                float hy = acc[mt][nb][hrow * 2 + 1];
                sv.x = 0.9f * sv.x + hx;  mv.x = 0.85f * mv.x + sv.x;
                sv.y = 0.9f * sv.y + hy;  mv.y = 0.85f * mv.y + sv.y;
                if (MODE == 1) {
                    float px = (mv.x > 1.f) ? 1.f : 0.f;  mv.x = (mv.x > 1.f) ? 0.f : mv.x;
                    float py = (mv.y > 1.f) ? 1.f : 0.f;  mv.y = (mv.y > 1.f) ? 0.f : mv.y;
                    *(__half2*)(spk_out + ix) = __floats2half2_rn(px, py);
                }
                *(float2*)(S + ix) = sv;
                *(float2*)(M + ix) = mv;
            }
}

// ============================================================
// launch — forked-stream pipeline (g2(t) on s2; g1(t+1) overlaps g2(t))
// ============================================================
extern "C" void kernel_launch(void* const* d_in, const int* in_sizes, int n_in,
                              void* d_out, int out_size) {
    (void)in_sizes; (void)n_in; (void)out_size;
    const float* inp = (const float*)d_in[0];   // [16384, 128]
    const float* W0  = (const float*)d_in[1];   // [256, 512]
    const float* W1  = (const float*)d_in[2];   // [512, 512]
    const float* W2  = (const float*)d_in[3];   // [512, 512]
    float* out = (float*)d_out;                 // m2 state [16384, 512]

    static cudaStream_t s2 = nullptr;
    static cudaEvent_t e1[2], e2[2];
    if (s2 == nullptr) {
        cudaStreamCreateWithFlags(&s2, cudaStreamNonBlocking);
        for (int i = 0; i < 2; i++) {
            cudaEventCreateWithFlags(&e1[i], cudaEventDisableTiming);
            cudaEventCreateWithFlags(&e2[i], cudaEventDisableTiming);
        }
        cudaFuncSetAttribute(gemm_mma<1>,
                             cudaFuncAttributeMaxDynamicSharedMemorySize, SMEM_NEED);
        cudaFuncSetAttribute(gemm_mma<2>,
                             cudaFuncAttributeMaxDynamicSharedMemorySize, SMEM_NEED);
    }

    __half* d_spk0all;  cudaGetSymbolAddress((void**)&d_spk0all, g_spk0all);
    __half* d_spk1a;    cudaGetSymbolAddress((void**)&d_spk1a, g_spk1a);
    __half* d_spk1b;    cudaGetSymbolAddress((void**)&d_spk1b, g_spk1b);
    __half* spk1buf[2] = {d_spk1a, d_spk1b};

    zero_kernel<<<(NELEM / 4) / 256, 256>>>((float4*)out);
    prep_kernel<1><<<1024, 256>>>(W1);
    prep_kernel<2><<<1024, 256>>>(W2);
    gemm0_kernel<<<dim3(128, 4), 256>>>(inp, W0);
    spikes0_kernel<<<NELEM / 256, 256>>>();

    dim3 grid(128, 4);
    for (int t = 0; t < NSTEP; t++) {
        const int par = t & 1;
        if (t >= 2)
            cudaStreamWaitEvent(cudaStreamPerThread, e2[par], 0);
        gemm_mma<1><<<grid, 256, SMEM_NEED>>>(
            d_spk0all + (size_t)t * NELEM, spk1buf[par], nullptr);
        cudaEventRecord(e1[par], cudaStreamPerThread);
        cudaStreamWaitEvent(s2, e1[par], 0);
        gemm_mma<2><<<grid, 256, SMEM_NEED, s2>>>(spk1buf[par], nullptr, out);
        cudaEventRecord(e2[par], s2);
    }
    cudaStreamWaitEvent(cudaStreamPerThread, e2[0], 0);
    cudaStreamWaitEvent(cudaStreamPerThread, e2[1], 0);
}

// round 13
// speedup vs baseline: 1.9262x; 1.0176x over previous
#include <cuda_runtime.h>
#include <cuda_fp16.h>
#include <cstdint>

// ============================================================
// 3-layer SNN. B=16384, H=512, 127 steps.
// R13 = R12 with the stream-capture fork bug fixed: s2/s3 enter the capture
// via cudaStreamWaitEvent on an event recorded in the main stream BEFORE
// any launch on them (capture-fork rule).
//  - setup overlap: W-prep on s2; spikes0 split at t=8, tail on s3 with an
//    fp32 carry (identical arithmetic), g1(8) gated by event
//  - L2 prefetch of S/M epilogue tiles at gemm start
//  - mainloop/t-loop identical to R11 (best passing: 17.0ms)
// Expect bit-identical rel_err 1.011837e-4.
// ============================================================

constexpr int NSTEP = 127;
constexpr int TSPLIT = 8;              // spikes0 split point
constexpr int NELEM = 16384 * 512;

__device__ float g_h0[NELEM];
__device__ float g_mc[NELEM];          // layer-0 membrane carry at t=TSPLIT
__device__ float g_s1[NELEM];
__device__ float g_m1[NELEM];
__device__ float g_s2[NELEM];
__device__ __half g_spk0all[(size_t)NSTEP * NELEM];   // 2.13GB
__device__ __half g_spk1a[NELEM];
__device__ __half g_spk1b[NELEM];
__device__ __half g_W1t[2][512 * 512];   // [split][N][K] K-contiguous
__device__ __half g_W2t[2][512 * 512];

// ---- PTX helpers (sm_80-class, valid at sm_103 base target) ----
__device__ __forceinline__ uint32_t smem_to_u32(const void* p) {
    uint32_t a;
    asm("{ .reg .u64 t; cvta.to.shared.u64 t, %1; cvt.u32.u64 %0, t; }"
        : "=r"(a) : "l"(p));
    return a;
}
__device__ __forceinline__ void cp16(uint32_t dst, const void* src) {
    asm volatile("cp.async.cg.shared.global [%0], [%1], 16;"
                 :: "r"(dst), "l"(src) : "memory");
}
#define CP_COMMIT() asm volatile("cp.async.commit_group;" ::: "memory")
#define CP_WAIT(N)  asm volatile("cp.async.wait_group %0;" :: "n"(N) : "memory")
__device__ __forceinline__ void l2_prefetch(const void* p) {
    asm volatile("prefetch.global.L2 [%0];" :: "l"(p));
}

__device__ __forceinline__ void ldm4(uint32_t& r0, uint32_t& r1, uint32_t& r2,
                                     uint32_t& r3, uint32_t addr) {
    asm volatile("ldmatrix.sync.aligned.m8n8.x4.shared.b16 {%0,%1,%2,%3}, [%4];"
                 : "=r"(r0), "=r"(r1), "=r"(r2), "=r"(r3) : "r"(addr));
}
__device__ __forceinline__ void mma16816(float* c, const uint32_t* a,
                                         uint32_t b0, uint32_t b1) {
    asm volatile(
        "mma.sync.aligned.m16n8k16.row.col.f32.f16.f16.f32 "
        "{%0,%1,%2,%3}, {%4,%5,%6,%7}, {%8,%9}, {%0,%1,%2,%3};"
        : "+f"(c[0]), "+f"(c[1]), "+f"(c[2]), "+f"(c[3])
        : "r"(a[0]), "r"(a[1]), "r"(a[2]), "r"(a[3]), "r"(b0), "r"(b1));
}
#define SWZ64(x) ((x) ^ (((x) >> 3) & 0x30))

// ============================================================
// one-time kernels
// ============================================================
__global__ void zero_kernel(float4* __restrict__ out) {
    int i = blockIdx.x * blockDim.x + threadIdx.x;
    float4 z = make_float4(0.f, 0.f, 0.f, 0.f);
    ((float4*)g_s1)[i] = z;
    ((float4*)g_m1)[i] = z;
    ((float4*)g_s2)[i] = z;
    out[i] = z;
}

// exact 2-way fp16 split + transpose of W [512K x 512N] -> Wt[2][N][K]
template <int WHICH>
__global__ void prep_kernel(const float* __restrict__ Wsrc) {
    int idx = blockIdx.x * blockDim.x + threadIdx.x;  // over 512*512
    int k = idx >> 9, n = idx & 511;
    float w = Wsrc[idx];
    __half hi = __float2half_rn(w);
    __half lo = __float2half_rn(w - __half2float(hi));
    __half (*dst)[512 * 512] = (WHICH == 1) ? g_W1t : g_W2t;
    int t = n * 512 + k;
    dst[0][t] = hi;
    dst[1][t] = lo;
}

// layer-0 LIF trajectories, t in [T0, T1). PART A writes the carry;
// PART B resumes from it — identical per-element arithmetic.
template <int T0, int T1, bool WRITE_CARRY>
__global__ void spikes0_kernel() {
    int idx = blockIdx.x * blockDim.x + threadIdx.x;  // over NELEM
    float h = g_h0[idx];
    float m = (T0 == 0) ? 0.f : g_mc[idx];
#pragma unroll 1
    for (int t = T0; t < T1; t++) {
        m = 0.85f * m + h;
        bool p = m > 1.0f;
        g_spk0all[(size_t)t * NELEM + idx] = p ? __float2half(1.f)
                                               : __float2half(0.f);
        if (p) m = 0.f;
    }
    if (WRITE_CARRY) g_mc[idx] = m;
}

// ============================================================
// layer-0 drive: h0 = relu_concat(inputs) @ W0 (fp32, runs once)
// ============================================================
__global__ __launch_bounds__(256)
void gemm0_kernel(const float* __restrict__ Aext, const float* __restrict__ W) {
    constexpr int KT = 8, NK = 256 / KT;
    __shared__ float As[2][KT][128];
    __shared__ float Bs[2][KT][128];
    const int row0 = blockIdx.x * 128, col0 = blockIdx.y * 128;
    const int tid = threadIdx.x;
    const int tx = tid & 15, ty = tid >> 4;
    const int ar = tid >> 1, aq = (tid & 1) * 4;
    const int bk = tid >> 5, bj = (tid & 31) * 4;

    float acc[8][8];
#pragma unroll
    for (int i = 0; i < 8; i++)
#pragma unroll
        for (int j = 0; j < 8; j++) acc[i][j] = 0.f;

    float4 ra, rb;
    auto LOADG = [&](int k0) {
        int kk = k0 + aq;
        if (kk < 128) {
            float4 v = *(const float4*)(Aext + (size_t)(row0 + ar) * 128 + kk);
            ra.x = fmaxf(v.x, 0.f); ra.y = fmaxf(v.y, 0.f);
            ra.z = fmaxf(v.z, 0.f); ra.w = fmaxf(v.w, 0.f);
        } else {
            float4 v = *(const float4*)(Aext + (size_t)(row0 + ar) * 128 + (kk - 128));
            ra.x = fmaxf(-v.x, 0.f); ra.y = fmaxf(-v.y, 0.f);
            ra.z = fmaxf(-v.z, 0.f); ra.w = fmaxf(-v.w, 0.f);
        }
        rb = *(const float4*)(W + (size_t)(k0 + bk) * 512 + col0 + bj);
    };
    auto STORES = [&](int buf) {
        As[buf][aq + 0][ar] = ra.x; As[buf][aq + 1][ar] = ra.y;
        As[buf][aq + 2][ar] = ra.z; As[buf][aq + 3][ar] = ra.w;
        *(float4*)&Bs[buf][bk][bj] = rb;
    };

    LOADG(0); STORES(0); __syncthreads();
    for (int kt = 0; kt < NK; kt++) {
        const int buf = kt & 1;
        if (kt + 1 < NK) LOADG((kt + 1) * KT);
#pragma unroll
        for (int k = 0; k < KT; k++) {
            float4 a0 = *(const float4*)&As[buf][k][ty * 8];
            float4 a1 = *(const float4*)&As[buf][k][ty * 8 + 4];
            float4 b0 = *(const float4*)&Bs[buf][k][tx * 8];
            float4 b1 = *(const float4*)&Bs[buf][k][tx * 8 + 4];
            float av[8] = {a0.x, a0.y, a0.z, a0.w, a1.x, a1.y, a1.z, a1.w};
            float bv[8] = {b0.x, b0.y, b0.z, b0.w, b1.x, b1.y, b1.z, b1.w};
#pragma unroll
            for (int i = 0; i < 8; i++)
#pragma unroll
                for (int j = 0; j < 8; j++) acc[i][j] = fmaf(av[i], bv[j], acc[i][j]);
        }
        if (kt + 1 < NK) STORES(buf ^ 1);
        __syncthreads();
    }
    const int r0 = row0 + ty * 8, c0 = col0 + tx * 8;
#pragma unroll
    for (int i = 0; i < 8; i++) {
        size_t base = (size_t)(r0 + i) * 512 + c0;
        *(float4*)&g_h0[base]     = make_float4(acc[i][0], acc[i][1], acc[i][2], acc[i][3]);
        *(float4*)&g_h0[base + 4] = make_float4(acc[i][4], acc[i][5], acc[i][6], acc[i][7]);
    }
}

// ============================================================
// HMMA GEMM + fused LIF epilogue
// Tile M=128 x N=128; K=512 in 16 chunks of 32; 2 fp16 W-splits.
// 4-stage cp.async pipeline (prefetch depth 3, wait_group 2), one barrier
// per chunk. SW64. 8 warps, warp tile 64x32. S/M tiles L2-prefetched.
// ============================================================
constexpr int STAGE_BYTES = 24576;
constexpr int SMEM_NEED   = 4 * STAGE_BYTES;   // 96KB -> 2 CTAs/SM

template <int MODE>
__global__ __launch_bounds__(256, 2)
void gemm_mma(const __half* __restrict__ A, __half* __restrict__ spk_out,
              float* __restrict__ Mext) {
    extern __shared__ char smem[];
    const int tid = threadIdx.x;
    const int wid = tid >> 5, lane = tid & 31;
    const int warp_m = wid & 1, warp_n = wid >> 1;
    const int row0 = blockIdx.x * 128, col0 = blockIdx.y * 128;

    const __half* W = (MODE == 1) ? &g_W1t[0][0] : &g_W2t[0][0];
    const uint32_t sb = smem_to_u32(smem);

    auto load_chunk = [&](int c, int s) {
        const uint32_t ap = sb + s * STAGE_BYTES;
        const uint32_t bp = ap + 8192;
        const int k0 = c * 32;
#pragma unroll
        for (int j = 0; j < 2; j++) {                  // A: 512 x 16B
            int i = tid + j * 256;
            int r = i >> 2, q = i & 3;
            cp16(ap + SWZ64(r * 64 + q * 16),
                 A + (size_t)(row0 + r) * 512 + k0 + q * 8);
        }
#pragma unroll
        for (int j = 0; j < 4; j++) {                  // B: 2 x 512 x 16B
            int i = tid + j * 256;
            int sp = i >> 9, rem = i & 511;
            int n = rem >> 2, q = rem & 3;
            cp16(bp + sp * 8192 + SWZ64(n * 64 + q * 16),
                 W + (size_t)sp * 262144 + (size_t)(col0 + n) * 512 + k0 + q * 8);
        }
        CP_COMMIT();
    };

    load_chunk(0, 0);
    load_chunk(1, 1);
    load_chunk(2, 2);

    // warm L2 with this tile's epilogue state (row tid>>1, 64-col half tid&1)
    {
        const float* S = (MODE == 1) ? g_s1 : g_s2;
        const float* M = (MODE == 1) ? g_m1 : Mext;
        size_t pix = (size_t)(row0 + (tid >> 1)) * 512 + col0 + (tid & 1) * 64;
        l2_prefetch(S + pix);  l2_prefetch(S + pix + 32);
        l2_prefetch(M + pix);  l2_prefetch(M + pix + 32);
    }

    float acc[4][4][4];
#pragma unroll
    for (int mt = 0; mt < 4; mt++)
#pragma unroll
        for (int nb = 0; nb < 4; nb++)
#pragma unroll
            for (int e = 0; e < 4; e++) acc[mt][nb][e] = 0.f;

    const int mat = lane >> 3, mrr = lane & 7;

#pragma unroll 1
    for (int c = 0; c < 16; c++) {
        const int s = c & 3;
        if (c <= 13)      CP_WAIT(2);
        else if (c == 14) CP_WAIT(1);
        else              CP_WAIT(0);
        __syncthreads();                       // single barrier per chunk
        if (c + 3 < 16) load_chunk(c + 3, (c + 3) & 3);

        const uint32_t ab = sb + s * STAGE_BYTES;
        const uint32_t bb = ab + 8192;
#pragma unroll
        for (int k16 = 0; k16 < 2; k16++) {
            const int k0 = k16 * 16;
            uint32_t a[4][4];
#pragma unroll
            for (int mt = 0; mt < 4; mt++) {
                int row = warp_m * 64 + mt * 16 + (mat & 1) * 8 + mrr;
                int kk  = k0 + (mat >> 1) * 8;
                ldm4(a[mt][0], a[mt][1], a[mt][2], a[mt][3],
                     ab + SWZ64(row * 64 + kk * 2));
            }
#pragma unroll
            for (int sp = 0; sp < 2; sp++) {
                uint32_t b[2][4];
#pragma unroll
                for (int n2 = 0; n2 < 2; n2++) {
                    int n  = warp_n * 32 + n2 * 16 + (mat >> 1) * 8 + mrr;
                    int kk = k0 + (mat & 1) * 8;
                    ldm4(b[n2][0], b[n2][1], b[n2][2], b[n2][3],
                         bb + sp * 8192 + SWZ64(n * 64 + kk * 2));
                }
#pragma unroll
                for (int mt = 0; mt < 4; mt++)
#pragma unroll
                    for (int nb = 0; nb < 4; nb++)
                        mma16816(acc[mt][nb], a[mt],
                                 b[nb >> 1][(nb & 1) * 2],
                                 b[nb >> 1][(nb & 1) * 2 + 1]);
            }
        }
    }

    // ---- fused LIF epilogue, direct from mma fragments ----
    float* S = (MODE == 1) ? g_s1 : g_s2;
    float* M = (MODE == 1) ? g_m1 : Mext;
    const int er = row0 + warp_m * 64 + (lane >> 2);
    const int ec = col0 + warp_n * 32 + (lane & 3) * 2;
#pragma unroll
    for (int mt = 0; mt < 4; mt++)
#pragma unroll
        for (int nb = 0; nb < 4; nb++)
#pragma unroll
            for (int hrow = 0; hrow < 2; hrow++) {
                size_t ix = (size_t)(er + mt * 16 + hrow * 8) * 512 + ec + nb * 8;
                float2 sv = *(const float2*)(S + ix);
                float2 mv = *(const float2*)(M + ix);
                float hx = acc[mt][nb][hrow * 2 + 0];
                float hy = acc[mt][nb][hrow * 2 + 1];
                sv.x = 0.9f * sv.x + hx;  mv.x = 0.85f * mv.x + sv.x;
                sv.y = 0.9f * sv.y + hy;  mv.y = 0.85f * mv.y + sv.y;
                if (MODE == 1) {
                    float px = (mv.x > 1.f) ? 1.f : 0.f;  mv.x = (mv.x > 1.f) ? 0.f : mv.x;
                    float py = (mv.y > 1.f) ? 1.f : 0.f;  mv.y = (mv.y > 1.f) ? 0.f : mv.y;
                    *(__half2*)(spk_out + ix) = __floats2half2_rn(px, py);
                }
                *(float2*)(S + ix) = sv;
                *(float2*)(M + ix) = mv;
            }
}

// ============================================================
// launch — forked-stream pipeline + overlapped setup.
// Capture-fork rule: s2/s3's FIRST captured op is a waitEvent on an event
// recorded in the main (origin) stream.
// ============================================================
extern "C" void kernel_launch(void* const* d_in, const int* in_sizes, int n_in,
                              void* d_out, int out_size) {
    (void)in_sizes; (void)n_in; (void)out_size;
    const float* inp = (const float*)d_in[0];   // [16384, 128]
    const float* W0  = (const float*)d_in[1];   // [256, 512]
    const float* W1  = (const float*)d_in[2];   // [512, 512]
    const float* W2  = (const float*)d_in[3];   // [512, 512]
    float* out = (float*)d_out;                 // m2 state [16384, 512]

    static cudaStream_t s2 = nullptr, s3 = nullptr;
    static cudaEvent_t e1[2], e2[2], eFork, ePrep, eA, e0;
    if (s2 == nullptr) {
        cudaStreamCreateWithFlags(&s2, cudaStreamNonBlocking);
        cudaStreamCreateWithFlags(&s3, cudaStreamNonBlocking);
        for (int i = 0; i < 2; i++) {
            cudaEventCreateWithFlags(&e1[i], cudaEventDisableTiming);
            cudaEventCreateWithFlags(&e2[i], cudaEventDisableTiming);
        }
        cudaEventCreateWithFlags(&eFork, cudaEventDisableTiming);
        cudaEventCreateWithFlags(&ePrep, cudaEventDisableTiming);
        cudaEventCreateWithFlags(&eA, cudaEventDisableTiming);
        cudaEventCreateWithFlags(&e0, cudaEventDisableTiming);
        cudaFuncSetAttribute(gemm_mma<1>,
                             cudaFuncAttributeMaxDynamicSharedMemorySize, SMEM_NEED);
        cudaFuncSetAttribute(gemm_mma<2>,
                             cudaFuncAttributeMaxDynamicSharedMemorySize, SMEM_NEED);
    }

    __half* d_spk0all;  cudaGetSymbolAddress((void**)&d_spk0all, g_spk0all);
    __half* d_spk1a;    cudaGetSymbolAddress((void**)&d_spk1a, g_spk1a);
    __half* d_spk1b;    cudaGetSymbolAddress((void**)&d_spk1b, g_spk1b);
    __half* spk1buf[2] = {d_spk1a, d_spk1b};

    // ---- fork point: first captured op, recorded in the ORIGIN stream ----
    zero_kernel<<<(NELEM / 4) / 256, 256>>>((float4*)out);
    cudaEventRecord(eFork, cudaStreamPerThread);

    // s2 joins the capture via waitEvent, THEN launches (capture-fork rule)
    cudaStreamWaitEvent(s2, eFork, 0);
    prep_kernel<1><<<1024, 256, 0, s2>>>(W1);
    prep_kernel<2><<<1024, 256, 0, s2>>>(W2);
    cudaEventRecord(ePrep, s2);

    // main stream: layer-0 drive + head of the spike trajectories
    gemm0_kernel<<<dim3(128, 4), 256>>>(inp, W0);
    spikes0_kernel<0, TSPLIT, true><<<NELEM / 256, 256>>>();
    cudaEventRecord(eA, cudaStreamPerThread);

    // s3 joins via waitEvent, then computes the trajectory tail
    cudaStreamWaitEvent(s3, eA, 0);
    spikes0_kernel<TSPLIT, NSTEP, false><<<NELEM / 256, 256, 0, s3>>>();
    cudaEventRecord(e0, s3);

    cudaStreamWaitEvent(cudaStreamPerThread, ePrep, 0);  // W1t ready for g1

    // ---- main t-loop ----
    dim3 grid(128, 4);
    for (int t = 0; t < NSTEP; t++) {
        const int par = t & 1;
        if (t == TSPLIT)
            cudaStreamWaitEvent(cudaStreamPerThread, e0, 0);
        if (t >= 2)
            cudaStreamWaitEvent(cudaStreamPerThread, e2[par], 0);
        gemm_mma<1><<<grid, 256, SMEM_NEED>>>(
            d_spk0all + (size_t)t * NELEM, spk1buf[par], nullptr);
        cudaEventRecord(e1[par], cudaStreamPerThread);
        cudaStreamWaitEvent(s2, e1[par], 0);
        gemm_mma<2><<<grid, 256, SMEM_NEED, s2>>>(spk1buf[par], nullptr, out);
        cudaEventRecord(e2[par], s2);
    }
    cudaStreamWaitEvent(cudaStreamPerThread, e2[0], 0);
    cudaStreamWaitEvent(cudaStreamPerThread, e2[1], 0);
}